// round 10
// baseline (speedup 1.0000x reference)
#include <cuda_runtime.h>
#include <cstdint>

#define NB     16
#define NTAU   10
#define ND     6
#define NN     512
#define NW     9
#define NHID   64
#define KC     54
#define TILE_M 64
#define NTILE  128          // 8192 tokens / 64
#define CHUNK  64           // tiles per chunk
#define PTPB   288
#define GTPB   256
#define DYN_BYTES (65536 + 128)

typedef unsigned long long ull;

// W0 pre-converted: [i*10+t] 16KB (8KB hi + 8KB lo), swizzled [n][kk] bf16
__device__ __align__(1024) unsigned char g_w0bf[60 * 16384];
// A scratch: per (tile, itx): 16KB (8KB hi + 8KB lo), swizzled [row][kk] bf16
__device__ __align__(1024) unsigned char g_a[(size_t)NTILE * 60 * 16384];

__device__ __forceinline__ uint32_t smem_u32(const void* p) {
    uint32_t a;
    asm("{ .reg .u64 t; cvta.to.shared.u64 t, %1; cvt.u32.u64 %0, t; }" : "=r"(a) : "l"(p));
    return a;
}
__device__ __forceinline__ ull ffma2(ull a, ull b, ull c) {
    ull d; asm("fma.rn.f32x2 %0, %1, %2, %3;" : "=l"(d) : "l"(a), "l"(b), "l"(c)); return d;
}
__device__ __forceinline__ ull pack2(float x) {
    ull d; asm("mov.b64 %0, {%1, %1};" : "=l"(d) : "f"(x)); return d;
}
__device__ __forceinline__ float2 unpack2(ull v) {
    float2 r; asm("mov.b64 {%0, %1}, %2;" : "=f"(r.x), "=f"(r.y) : "l"(v)); return r;
}
__device__ __forceinline__ uint32_t f2bf_bits(float v) {   // RNE bf16
    uint32_t u = __float_as_uint(v);
    return (u + 0x7FFFu + ((u >> 16) & 1u)) >> 16;
}
__device__ __forceinline__ uint32_t cvt_bf16x2(float hi, float lo) {
    uint32_t r; asm("cvt.rn.bf16x2.f32 %0, %1, %2;" : "=r"(r) : "f"(hi), "f"(lo)); return r;
}
__device__ __forceinline__ float2 ldcs2(const float2* p) {
    float2 r; asm volatile("ld.global.cs.v2.f32 {%0,%1}, [%2];" : "=f"(r.x), "=f"(r.y) : "l"(p)); return r;
}
__device__ __forceinline__ void ldsm4(uint32_t a, uint32_t& r0, uint32_t& r1, uint32_t& r2, uint32_t& r3) {
    asm volatile("ldmatrix.sync.aligned.m8n8.x4.shared.b16 {%0,%1,%2,%3}, [%4];"
                 : "=r"(r0), "=r"(r1), "=r"(r2), "=r"(r3) : "r"(a));
}
__device__ __forceinline__ void mma_bf16(float* d, uint32_t a0, uint32_t a1, uint32_t a2, uint32_t a3,
                                         uint32_t b0, uint32_t b1) {
    asm volatile("mma.sync.aligned.m16n8k16.row.col.f32.bf16.bf16.f32 "
                 "{%0,%1,%2,%3}, {%4,%5,%6,%7}, {%8,%9}, {%0,%1,%2,%3};"
                 : "+f"(d[0]), "+f"(d[1]), "+f"(d[2]), "+f"(d[3])
                 : "r"(a0), "r"(a1), "r"(a2), "r"(a3), "r"(b0), "r"(b1));
}
#define CP16(dst, src) asm volatile("cp.async.cg.shared.global [%0], [%1], 16;" :: "r"(dst), "l"(src))
#define CP_COMMIT()    asm volatile("cp.async.commit_group;" ::: "memory")
#define CP_WAIT0()     asm volatile("cp.async.wait_group 0;" ::: "memory")
#define CP_WAIT1()     asm volatile("cp.async.wait_group 1;" ::: "memory")

// ------------ producer: m -> swizzled bf16 hi/lo A-tiles (+W0 prep on chunk 0) ------------
__global__ __launch_bounds__(PTPB) void produce_a(
    const float* __restrict__ x,
    const float* __restrict__ mask_param,
    const float* __restrict__ u,
    const float* __restrict__ W0,
    int tile_base, int do_w0)
{
    __shared__ float E_s[KC];
    __shared__ float x_s[6 * 12 * 17];
    __shared__ unsigned char lut_s[KC];

    const int tid  = threadIdx.x;
    const int tile = blockIdx.x + tile_base;
    const int itx  = blockIdx.y;          // i*10 + t
    const int i = itx / 10, t = itx % 10;
    const int tile0 = tile * TILE_M;
    const int n0 = tile0 >> 4;            // 4 n per tile

    if (do_w0 && blockIdx.x == 0) {
        const float* src = W0 + ((size_t)i * 540 + t * KC) * NHID;
        unsigned char* hi = g_w0bf + (size_t)itx * 16384;
        unsigned char* lo = hi + 8192;
        for (int e = tid; e < 4096; e += PTPB) {
            int kk = e >> 6, n = e & 63;
            float v = (kk < KC) ? src[kk * 64 + n] : 0.f;
            uint32_t hb = f2bf_bits(v);
            float hf = __uint_as_float(hb << 16);
            uint32_t lb = f2bf_bits(v - hf);
            uint32_t off = (uint32_t)(n * 128 + kk * 2) ^ ((uint32_t)(n & 7) << 4);
            *(uint16_t*)(hi + off) = (uint16_t)hb;
            *(uint16_t*)(lo + off) = (uint16_t)lb;
        }
    }

    if (tid < KC) {
        E_s[tid] = __expf(-mask_param[(t * ND + i) * KC + tid]);
        lut_s[tid] = (unsigned char)((tid / NW) * 12 + tid % NW);
    }
    // stage x window: x_s[(j*12+colw)*17 + b], 1152 elems = 4/thread
    #pragma unroll
    for (int e4 = 0; e4 < 4; ++e4) {
        int e = tid + e4 * PTPB;
        int colw = e % 12;
        int j = (e / 12) % 6;
        int bb = e / 72;
        int col = n0 + colw - 4;
        float v = 0.f;
        if ((unsigned)col < NN) v = x[((bb * NTAU + t) * ND + j) * NN + col];
        x_s[(j * 12 + colw) * 17 + bb] = v;
    }
    __syncthreads();

    // 1728 float2 = 6/thread exactly
    const float* ub = u + (size_t)(t * ND + i) * KC;
    float2 ur[6];
    #pragma unroll
    for (int it = 0; it < 6; ++it) {
        int p = tid + it * PTPB;
        int r = (p * 4855) >> 17;       // p/27 for p<3456
        int q = p - r * 27;
        ur[it] = ldcs2((const float2*)(ub + (size_t)(tile0 + r) * 3240 + 2 * q));
    }
    unsigned char* ahp = g_a + ((size_t)tile * 60 + itx) * 16384;
    #pragma unroll
    for (int it = 0; it < 6; ++it) {
        int p = tid + it * PTPB;
        int r = (p * 4855) >> 17;
        int q = p - r * 27;
        int kk = 2 * q;
        float2 uv = ur[it];
        float2 ev = *(const float2*)&E_s[kk];
        int nl = r >> 4, bb = r & 15;
        float x0 = x_s[(lut_s[kk] + nl) * 17 + bb];
        float x1 = x_s[(lut_s[kk + 1] + nl) * 17 + bb];
        float m0 = x0 * __fdividef(uv.x, fmaf(ev.x, 1.f - uv.x, uv.x));
        float m1 = x1 * __fdividef(uv.y, fmaf(ev.y, 1.f - uv.y, uv.y));
        uint32_t h2 = cvt_bf16x2(m1, m0);            // lo16 = m0
        float hf0 = __uint_as_float(h2 << 16);
        float hf1 = __uint_as_float(h2 & 0xFFFF0000u);
        uint32_t l2 = cvt_bf16x2(m1 - hf1, m0 - hf0);
        uint32_t off = (uint32_t)(r * 128 + 4 * q) ^ ((uint32_t)(r & 7) << 4);
        *(uint32_t*)(ahp + off)        = h2;
        *(uint32_t*)(ahp + 8192 + off) = l2;
    }
}

// ------------ consumer: GEMM (tensor cores) + layers 1/2; 3 CTAs/SM ------------
__global__ __launch_bounds__(GTPB, 3)
void gemm_mlp(const float* __restrict__ b0,
              const float* __restrict__ W1,
              const float* __restrict__ b1,
              const float* __restrict__ W2,
              const float* __restrict__ b2,
              float* __restrict__ out,
              int tile_base)
{
    extern __shared__ unsigned char dyn_raw[];
    __shared__ float b0_s[NHID], b1_s[NHID], W2_s[128], b2_s[2];
    __shared__ float2 po_s[GTPB];

    const uint32_t raw_u = smem_u32(dyn_raw);
    const uint32_t dynb  = (raw_u + 127u) & ~127u;
    unsigned char* dyn = dyn_raw + (dynb - raw_u);
    // layout: A0@0(16K: hi 0-8K, lo 8-16K), A1@16K, B0@32K, B1@48K

    const int tid  = threadIdx.x;
    const int w    = tid >> 5;
    const int lane = tid & 31;
    const int i    = blockIdx.y;
    const int tile = blockIdx.x + tile_base;
    const int tile0 = tile * TILE_M;

    if (tid < NHID) { b0_s[tid] = b0[i * NHID + tid]; b1_s[tid] = b1[i * NHID + tid]; }
    if (tid < 128) W2_s[tid] = W2[i * 128 + tid];
    if (tid < 2)   b2_s[tid] = b2[i * 2 + tid];

    float d[4][4];
    #pragma unroll
    for (int q = 0; q < 4; ++q)
        #pragma unroll
        for (int c = 0; c < 4; ++c) d[q][c] = 0.f;

    // warp -> 16-row group (rg) x 32-col half (nh)
    const int rg = w & 3;
    const int nh = w >> 2;
    const int rowA = rg * 16 + (lane & 15);
    const uint32_t arow = (uint32_t)rowA * 128;
    const uint32_t axr  = (uint32_t)(rowA & 7) << 4;
    const uint32_t colsel = (uint32_t)(lane >> 4) << 4;

    auto prefetch = [&](int t) {
        const unsigned char* asrc = g_a + ((size_t)tile * 60 + i * 10 + t) * 16384;
        uint32_t adst = dynb + (uint32_t)(t & 1) * 16384;
        #pragma unroll
        for (int c = 0; c < 4; ++c)
            CP16(adst + tid * 16 + c * 4096, asrc + tid * 16 + c * 4096);
        const unsigned char* bsrc = g_w0bf + (size_t)(i * 10 + t) * 16384;
        uint32_t bdst = dynb + 32768 + (uint32_t)(t & 1) * 16384;
        #pragma unroll
        for (int c = 0; c < 4; ++c)
            CP16(bdst + tid * 16 + c * 4096, bsrc + tid * 16 + c * 4096);
        CP_COMMIT();
    };
    auto consume = [&](int s) {
        uint32_t Abase = dynb + (uint32_t)s * 16384;
        uint32_t Bbase = dynb + 32768 + (uint32_t)s * 16384;
        #pragma unroll
        for (int k = 0; k < 4; ++k) {
            uint32_t colb = (uint32_t)k * 32 + colsel;
            uint32_t aa = Abase + arow + (colb ^ axr);
            uint32_t ah0, ah1, ah2, ah3, al0, al1, al2, al3;
            ldsm4(aa,        ah0, ah1, ah2, ah3);
            ldsm4(aa + 8192, al0, al1, al2, al3);
            #pragma unroll
            for (int g2 = 0; g2 < 2; ++g2) {
                int nrow = nh * 32 + g2 * 16 + (lane & 15);
                uint32_t ba = Bbase + (uint32_t)nrow * 128 + (colb ^ ((uint32_t)(nrow & 7) << 4));
                uint32_t bh0, bh1, bh2, bh3, bl0, bl1, bl2, bl3;
                ldsm4(ba,        bh0, bh1, bh2, bh3);
                ldsm4(ba + 8192, bl0, bl1, bl2, bl3);
                mma_bf16(d[2 * g2],     ah0, ah1, ah2, ah3, bh0, bh2);
                mma_bf16(d[2 * g2],     al0, al1, al2, al3, bh0, bh2);
                mma_bf16(d[2 * g2],     ah0, ah1, ah2, ah3, bl0, bl2);
                mma_bf16(d[2 * g2 + 1], ah0, ah1, ah2, ah3, bh1, bh3);
                mma_bf16(d[2 * g2 + 1], al0, al1, al2, al3, bh1, bh3);
                mma_bf16(d[2 * g2 + 1], ah0, ah1, ah2, ah3, bl1, bl3);
            }
        }
    };

    prefetch(0);
    prefetch(1);
    for (int t = 0; t < NTAU; ++t) {
        if (t < NTAU - 1) CP_WAIT1(); else CP_WAIT0();
        __syncthreads();
        consume(t & 1);
        __syncthreads();
        if (t < NTAU - 2) prefetch(t + 2);
    }

    // ---------- epilogue: bias+relu -> h_s (64 rows, stride 68) ----------
    {
        float* hs = (float*)dyn;
        int r0 = rg * 16 + (lane >> 2);
        int c0 = nh * 32 + 2 * (lane & 3);
        #pragma unroll
        for (int oct = 0; oct < 4; ++oct) {
            int c = c0 + 8 * oct;
            float ba = b0_s[c], bbv = b0_s[c + 1];
            *(float2*)&hs[r0 * 68 + c]       = make_float2(fmaxf(d[oct][0] + ba, 0.f), fmaxf(d[oct][1] + bbv, 0.f));
            *(float2*)&hs[(r0 + 8) * 68 + c] = make_float2(fmaxf(d[oct][2] + ba, 0.f), fmaxf(d[oct][3] + bbv, 0.f));
        }
        const unsigned char* w1src = (const unsigned char*)(W1 + (size_t)i * NHID * NHID);
        uint32_t w1dst = dynb + 32768;   // B0 region (16KB)
        #pragma unroll
        for (int c = 0; c < 4; ++c)
            CP16(w1dst + tid * 16 + c * 4096, w1src + tid * 16 + c * 4096);
        CP_COMMIT();
        CP_WAIT0();
    }
    __syncthreads();

    // ---------- layers 1+2: 4 threads/token, each a 16-wide g-slice ----------
    {
        const float* hs  = (const float*)dyn;
        const float* W1s = (const float*)(dyn + 32768);
        int rloc = tid >> 2;              // token row 0..63
        int gq   = tid & 3;               // g-slice [16gq, 16gq+16)
        const float* hrow = hs + rloc * 68;
        ull acc2[8];
        #pragma unroll
        for (int p = 0; p < 8; ++p) acc2[p] = 0ULL;
        #pragma unroll 8
        for (int k = 0; k < NHID; ++k) {
            ull hdup = pack2(hrow[k]);
            const ulonglong2* wr = (const ulonglong2*)(W1s + k * NHID + gq * 16);
            #pragma unroll
            for (int q = 0; q < 4; ++q) {
                ulonglong2 wv = wr[q];
                acc2[2 * q]     = ffma2(hdup, wv.x, acc2[2 * q]);
                acc2[2 * q + 1] = ffma2(hdup, wv.y, acc2[2 * q + 1]);
            }
        }
        float o0 = 0.f, o1 = 0.f;
        #pragma unroll
        for (int p = 0; p < 8; ++p) {
            float2 v = unpack2(acc2[p]);
            int g0 = gq * 16 + 2 * p;
            float v0 = fmaxf(v.x + b1_s[g0], 0.f);
            float v1 = fmaxf(v.y + b1_s[g0 + 1], 0.f);
            o0 = fmaf(v0, W2_s[g0 * 2],     o0);
            o1 = fmaf(v0, W2_s[g0 * 2 + 1], o1);
            o0 = fmaf(v1, W2_s[g0 * 2 + 2], o0);
            o1 = fmaf(v1, W2_s[g0 * 2 + 3], o1);
        }
        po_s[tid] = make_float2(o0, o1);
    }
    __syncthreads();
    if (tid < TILE_M) {
        float2 a0 = po_s[4 * tid],     a1 = po_s[4 * tid + 1];
        float2 a2 = po_s[4 * tid + 2], a3 = po_s[4 * tid + 3];
        int token = tile0 + tid;
        int bb = token & (NB - 1);
        int nn = token >> 4;
        ((float2*)out)[(size_t)(bb * ND + i) * NN + nn] =
            make_float2(a0.x + a1.x + a2.x + a3.x + b2_s[0],
                        a0.y + a1.y + a2.y + a3.y + b2_s[1]);
    }
}

extern "C" void kernel_launch(void* const* d_in, const int* in_sizes, int n_in,
                              void* d_out, int out_size)
{
    const float* x  = (const float*)d_in[0];
    const float* mp = (const float*)d_in[1];
    const float* u  = (const float*)d_in[2];
    const float* W0 = (const float*)d_in[3];
    const float* b0 = (const float*)d_in[4];
    const float* W1 = (const float*)d_in[5];
    const float* b1 = (const float*)d_in[6];
    const float* W2 = (const float*)d_in[7];
    const float* b2 = (const float*)d_in[8];
    float* out = (float*)d_out;

    static cudaStream_t s1;
    static cudaEvent_t evP[2], evG;
    static int inited = 0;
    if (!inited) {
        cudaFuncSetAttribute(gemm_mlp, cudaFuncAttributeMaxDynamicSharedMemorySize, DYN_BYTES);
        cudaStreamCreateWithFlags(&s1, cudaStreamNonBlocking);
        cudaEventCreateWithFlags(&evP[0], cudaEventDisableTiming);
        cudaEventCreateWithFlags(&evP[1], cudaEventDisableTiming);
        cudaEventCreateWithFlags(&evG, cudaEventDisableTiming);
        inited = 1;
    }

    // 2-chunk software pipeline: produce(c) on stream 0, gemm(c) on s1 gated by event
    for (int c = 0; c < 2; ++c) {
        produce_a<<<dim3(CHUNK, 60), PTPB, 0, 0>>>(x, mp, u, W0, c * CHUNK, c == 0);
        cudaEventRecord(evP[c], 0);
        cudaStreamWaitEvent(s1, evP[c], 0);
        gemm_mlp<<<dim3(CHUNK, ND), GTPB, DYN_BYTES, s1>>>(b0, W1, b1, W2, b2, out, c * CHUNK);
    }
    cudaEventRecord(evG, s1);
    cudaStreamWaitEvent(0, evG, 0);
}

// round 12
// speedup vs baseline: 1.1398x; 1.1398x over previous
#include <cuda_runtime.h>
#include <cstdint>

#define NB     16
#define NTAU   10
#define ND     6
#define NN     512
#define NW     9
#define NHID   64
#define KC     54
#define TILE_M 64
#define NTILE  128
#define TPB    256
#define DYN_BYTES (49152 + 128)

typedef unsigned long long ull;

// W0 pre-converted: [i*10+t] 16KB (8KB hi + 8KB lo), swizzled [n][kk] bf16
__device__ __align__(1024) unsigned char g_w0bf[60 * 16384];

__device__ __forceinline__ uint32_t smem_u32(const void* p) {
    uint32_t a;
    asm("{ .reg .u64 t; cvta.to.shared.u64 t, %1; cvt.u32.u64 %0, t; }" : "=r"(a) : "l"(p));
    return a;
}
__device__ __forceinline__ ull ffma2(ull a, ull b, ull c) {
    ull d; asm("fma.rn.f32x2 %0, %1, %2, %3;" : "=l"(d) : "l"(a), "l"(b), "l"(c)); return d;
}
__device__ __forceinline__ ull pack2(float x) {
    ull d; asm("mov.b64 %0, {%1, %1};" : "=l"(d) : "f"(x)); return d;
}
__device__ __forceinline__ float2 unpack2(ull v) {
    float2 r; asm("mov.b64 {%0, %1}, %2;" : "=f"(r.x), "=f"(r.y) : "l"(v)); return r;
}
__device__ __forceinline__ uint32_t f2bf_bits(float v) {   // RNE bf16
    uint32_t u = __float_as_uint(v);
    return (u + 0x7FFFu + ((u >> 16) & 1u)) >> 16;
}
__device__ __forceinline__ uint32_t cvt_bf16x2(float hi, float lo) {
    uint32_t r; asm("cvt.rn.bf16x2.f32 %0, %1, %2;" : "=r"(r) : "f"(hi), "f"(lo)); return r;
}
__device__ __forceinline__ float2 ldcs2(const float2* p) {
    float2 r; asm volatile("ld.global.cs.v2.f32 {%0,%1}, [%2];" : "=f"(r.x), "=f"(r.y) : "l"(p)); return r;
}
__device__ __forceinline__ void ldsm4(uint32_t a, uint32_t& r0, uint32_t& r1, uint32_t& r2, uint32_t& r3) {
    asm volatile("ldmatrix.sync.aligned.m8n8.x4.shared.b16 {%0,%1,%2,%3}, [%4];"
                 : "=r"(r0), "=r"(r1), "=r"(r2), "=r"(r3) : "r"(a));
}
__device__ __forceinline__ void mma_bf16(float* d, uint32_t a0, uint32_t a1, uint32_t a2, uint32_t a3,
                                         uint32_t b0, uint32_t b1) {
    asm volatile("mma.sync.aligned.m16n8k16.row.col.f32.bf16.bf16.f32 "
                 "{%0,%1,%2,%3}, {%4,%5,%6,%7}, {%8,%9}, {%0,%1,%2,%3};"
                 : "+f"(d[0]), "+f"(d[1]), "+f"(d[2]), "+f"(d[3])
                 : "r"(a0), "r"(a1), "r"(a2), "r"(a3), "r"(b0), "r"(b1));
}
#define CP16(dst, src) asm volatile("cp.async.cg.shared.global [%0], [%1], 16;" :: "r"(dst), "l"(src))
#define CP_COMMIT()    asm volatile("cp.async.commit_group;" ::: "memory")
#define CP_WAIT0()     asm volatile("cp.async.wait_group 0;" ::: "memory")

// ------------ prep: W0 -> swizzled bf16 hi/lo tile images (grid 60x4) ------------
__global__ void prep_w0(const float* __restrict__ W0)
{
    const int itx = blockIdx.x;                 // i*10 + t
    const int i = itx / 10, t = itx % 10;
    const float* src = W0 + ((size_t)i * 540 + t * KC) * NHID;
    unsigned char* hi = g_w0bf + (size_t)itx * 16384;
    unsigned char* lo = hi + 8192;
    int e0 = blockIdx.y * 1024 + threadIdx.x;
    #pragma unroll
    for (int c = 0; c < 4; ++c) {
        int e = e0 + c * 256;
        int kk = e >> 6, n = e & 63;
        float v = (kk < KC) ? src[kk * 64 + n] : 0.f;
        uint32_t hb = f2bf_bits(v);
        float hf = __uint_as_float(hb << 16);
        uint32_t lb = f2bf_bits(v - hf);
        uint32_t off = (uint32_t)(n * 128 + kk * 2) ^ ((uint32_t)(n & 7) << 4);
        *(uint16_t*)(hi + off) = (uint16_t)hb;
        *(uint16_t*)(lo + off) = (uint16_t)lb;
    }
}

// ------------ fused: produce m in smem + tensor GEMM + layers 1/2 ------------
__global__ __launch_bounds__(TPB, 3)
void tsdcd_fused(const float* __restrict__ x,
                 const float* __restrict__ mask_param,
                 const float* __restrict__ u,
                 const float* __restrict__ b0,
                 const float* __restrict__ W1,
                 const float* __restrict__ b1,
                 const float* __restrict__ W2,
                 const float* __restrict__ b2,
                 float* __restrict__ out)
{
    extern __shared__ unsigned char dyn_raw[];
    __shared__ float E_s[NTAU * KC];
    __shared__ float x_s[2][6 * 12 * 17];
    __shared__ float b0_s[NHID], b1_s[NHID], W2_s[128], b2_s[2];
    __shared__ unsigned char lut_s[KC];
    __shared__ float2 po_s[TPB];

    const uint32_t raw_u = smem_u32(dyn_raw);
    const uint32_t dynb  = (raw_u + 127u) & ~127u;
    unsigned char* dyn = dyn_raw + (dynb - raw_u);
    // layout: A @0 (16K: hi 0-8K, lo 8-16K), B0 @16K, B1 @32K

    const int tid  = threadIdx.x;
    const int w    = tid >> 5;
    const int lane = tid & 31;
    const int i    = blockIdx.y;
    const int tile = blockIdx.x;
    const int tile0 = tile * TILE_M;
    const int n0    = tile0 >> 4;     // 4 n per tile

    // ---- one-time staging ----
    {   // zero A tile: padding cols kk 54..63 MUST be 0 (never written by do_math)
        float4 z = make_float4(0.f, 0.f, 0.f, 0.f);
        float4* az = (float4*)dyn;
        #pragma unroll
        for (int e = tid; e < 1024; e += TPB) az[e] = z;
    }
    for (int e = tid; e < NTAU * KC; e += TPB) {
        int t = e / KC, r = e - t * KC;
        E_s[e] = __expf(-mask_param[(t * ND + i) * KC + r]);
    }
    if (tid < KC) lut_s[tid] = (unsigned char)((tid / NW) * 12 + tid % NW);
    if (tid < NHID) { b0_s[tid] = b0[i * NHID + tid]; b1_s[tid] = b1[i * NHID + tid]; }
    if (tid < 128) W2_s[tid] = W2[i * 128 + tid];
    if (tid < 2)   b2_s[tid] = b2[i * 2 + tid];

    float d[4][4];
    #pragma unroll
    for (int q = 0; q < 4; ++q)
        #pragma unroll
        for (int c = 0; c < 4; ++c) d[q][c] = 0.f;

    // per-lane ldmatrix geometry (4 row-groups x 2 n-halves)
    const int rg = w & 3;
    const int nh = w >> 2;
    const int rowA = rg * 16 + (lane & 15);
    const uint32_t arow = (uint32_t)rowA * 128;
    const uint32_t axr  = (uint32_t)(rowA & 7) << 4;
    const uint32_t colsel = (uint32_t)(lane >> 4) << 4;

    // ---- helpers ----
    auto stage_x = [&](int t) {   // ldg -> STS into x_s[t&1]
        float* xb = x_s[t & 1];
        #pragma unroll
        for (int it = 0; it < 5; ++it) {
            int e = tid + it * 256;
            if (e < 1152) {
                int colw = e % 12;
                int j = (e / 12) % 6;
                int bb = e / 72;
                int col = n0 + colw - 4;
                float v = 0.f;
                if ((unsigned)col < NN) v = x[((bb * NTAU + t) * ND + j) * NN + col];
                xb[(j * 12 + colw) * 17 + bb] = v;
            }
        }
    };
    auto load_u = [&](int t, float2* ur) {
        const float* ub = u + (size_t)(t * ND + i) * KC;
        #pragma unroll
        for (int it = 0; it < 7; ++it) {
            int p = tid + it * 256;
            if (p < 1728) {
                int r = (p * 4855) >> 17;     // p/27
                int q = p - r * 27;
                ur[it] = ldcs2((const float2*)(ub + (size_t)(tile0 + r) * 3240 + 2 * q));
            }
        }
    };
    auto cp_b = [&](int t) {
        const unsigned char* bsrc = g_w0bf + (size_t)(i * 10 + t) * 16384;
        uint32_t bdst = dynb + 16384 + (uint32_t)(t & 1) * 16384;
        #pragma unroll
        for (int c = 0; c < 4; ++c)
            CP16(bdst + tid * 16 + c * 4096, bsrc + tid * 16 + c * 4096);
        CP_COMMIT();
    };
    auto do_math = [&](int t, const float2* ur) {   // m -> STS A (hi/lo planes)
        const float* xb = x_s[t & 1];
        #pragma unroll
        for (int it = 0; it < 7; ++it) {
            int p = tid + it * 256;
            if (p < 1728) {
                int r = (p * 4855) >> 17;
                int q = p - r * 27;
                int kk = 2 * q;
                float2 uv = ur[it];
                float2 ev = *(const float2*)&E_s[t * KC + kk];
                int nl = r >> 4, bb = r & 15;
                float x0 = xb[(lut_s[kk] + nl) * 17 + bb];
                float x1 = xb[(lut_s[kk + 1] + nl) * 17 + bb];
                float m0 = x0 * __fdividef(uv.x, fmaf(ev.x, 1.f - uv.x, uv.x));
                float m1 = x1 * __fdividef(uv.y, fmaf(ev.y, 1.f - uv.y, uv.y));
                uint32_t h2 = cvt_bf16x2(m1, m0);           // lo16 = m0
                float hf0 = __uint_as_float(h2 << 16);
                float hf1 = __uint_as_float(h2 & 0xFFFF0000u);
                uint32_t l2 = cvt_bf16x2(m1 - hf1, m0 - hf0);
                uint32_t off = (uint32_t)(r * 128 + 4 * q) ^ ((uint32_t)(r & 7) << 4);
                *(uint32_t*)(dyn + off)        = h2;
                *(uint32_t*)(dyn + 8192 + off) = l2;
            }
        }
    };
    auto consume = [&](int t) {
        uint32_t Abase = dynb;
        uint32_t Bbase = dynb + 16384 + (uint32_t)(t & 1) * 16384;
        #pragma unroll
        for (int k = 0; k < 4; ++k) {
            uint32_t colb = (uint32_t)k * 32 + colsel;
            uint32_t aa = Abase + arow + (colb ^ axr);
            uint32_t ah0, ah1, ah2, ah3, al0, al1, al2, al3;
            ldsm4(aa,        ah0, ah1, ah2, ah3);
            ldsm4(aa + 8192, al0, al1, al2, al3);
            #pragma unroll
            for (int g2 = 0; g2 < 2; ++g2) {
                int nrow = nh * 32 + g2 * 16 + (lane & 15);
                uint32_t ba = Bbase + (uint32_t)nrow * 128 + (colb ^ ((uint32_t)(nrow & 7) << 4));
                uint32_t bh0, bh1, bh2, bh3, bl0, bl1, bl2, bl3;
                ldsm4(ba,        bh0, bh1, bh2, bh3);
                ldsm4(ba + 8192, bl0, bl1, bl2, bl3);
                mma_bf16(d[2 * g2],     ah0, ah1, ah2, ah3, bh0, bh2);
                mma_bf16(d[2 * g2],     al0, al1, al2, al3, bh0, bh2);
                mma_bf16(d[2 * g2],     ah0, ah1, ah2, ah3, bl0, bl2);
                mma_bf16(d[2 * g2 + 1], ah0, ah1, ah2, ah3, bh1, bh3);
                mma_bf16(d[2 * g2 + 1], al0, al1, al2, al3, bh1, bh3);
                mma_bf16(d[2 * g2 + 1], ah0, ah1, ah2, ah3, bl1, bl3);
            }
        }
    };

    // ---- mainloop: 2 barriers / t; u register-double-buffered ----
    float2 ur[2][7];
    cp_b(0);
    stage_x(0);
    load_u(0, ur[0]);
    #pragma unroll 2
    for (int t = 0; t < NTAU; ++t) {
        CP_WAIT0();                    // B(t) resident
        __syncthreads();               // barrier1: x_s(t)/A free (consume(t-1) done), B visible
        if (t + 1 < NTAU) {
            cp_b(t + 1);
            stage_x(t + 1);
            load_u(t + 1, ur[(t + 1) & 1]);
        }
        do_math(t, ur[t & 1]);
        __syncthreads();               // barrier2: A(t) visible
        consume(t);
    }
    __syncthreads();

    // ---- epilogue: bias+relu -> h_s (stride 68) @dyn+0; W1 -> @dyn+32K ----
    {
        float* hs = (float*)dyn;
        int r0 = rg * 16 + (lane >> 2);
        int c0 = nh * 32 + 2 * (lane & 3);
        #pragma unroll
        for (int oct = 0; oct < 4; ++oct) {
            int c = c0 + 8 * oct;
            float ba = b0_s[c], bbv = b0_s[c + 1];
            *(float2*)&hs[r0 * 68 + c]       = make_float2(fmaxf(d[oct][0] + ba, 0.f), fmaxf(d[oct][1] + bbv, 0.f));
            *(float2*)&hs[(r0 + 8) * 68 + c] = make_float2(fmaxf(d[oct][2] + ba, 0.f), fmaxf(d[oct][3] + bbv, 0.f));
        }
        const unsigned char* w1src = (const unsigned char*)(W1 + (size_t)i * NHID * NHID);
        uint32_t w1dst = dynb + 32768;
        #pragma unroll
        for (int c = 0; c < 4; ++c)
            CP16(w1dst + tid * 16 + c * 4096, w1src + tid * 16 + c * 4096);
        CP_COMMIT();
        CP_WAIT0();
    }
    __syncthreads();

    // ---- layers 1+2: 4 threads/token, each a 16-wide g-slice ----
    {
        const float* hs  = (const float*)dyn;
        const float* W1s = (const float*)(dyn + 32768);
        int rloc = tid >> 2;
        int gq   = tid & 3;
        const float* hrow = hs + rloc * 68;
        ull acc2[8];
        #pragma unroll
        for (int p = 0; p < 8; ++p) acc2[p] = 0ULL;
        #pragma unroll 8
        for (int k = 0; k < NHID; ++k) {
            ull hdup = pack2(hrow[k]);
            const ulonglong2* wr = (const ulonglong2*)(W1s + k * NHID + gq * 16);
            #pragma unroll
            for (int q = 0; q < 4; ++q) {
                ulonglong2 wv = wr[q];
                acc2[2 * q]     = ffma2(hdup, wv.x, acc2[2 * q]);
                acc2[2 * q + 1] = ffma2(hdup, wv.y, acc2[2 * q + 1]);
            }
        }
        float o0 = 0.f, o1 = 0.f;
        #pragma unroll
        for (int p = 0; p < 8; ++p) {
            float2 v = unpack2(acc2[p]);
            int g0 = gq * 16 + 2 * p;
            float v0 = fmaxf(v.x + b1_s[g0], 0.f);
            float v1 = fmaxf(v.y + b1_s[g0 + 1], 0.f);
            o0 = fmaf(v0, W2_s[g0 * 2],     o0);
            o1 = fmaf(v0, W2_s[g0 * 2 + 1], o1);
            o0 = fmaf(v1, W2_s[g0 * 2 + 2], o0);
            o1 = fmaf(v1, W2_s[g0 * 2 + 3], o1);
        }
        po_s[tid] = make_float2(o0, o1);
    }
    __syncthreads();
    if (tid < TILE_M) {
        float2 a0 = po_s[4 * tid],     a1 = po_s[4 * tid + 1];
        float2 a2 = po_s[4 * tid + 2], a3 = po_s[4 * tid + 3];
        int token = tile0 + tid;
        int bb = token & (NB - 1);
        int nn = token >> 4;
        ((float2*)out)[(size_t)(bb * ND + i) * NN + nn] =
            make_float2(a0.x + a1.x + a2.x + a3.x + b2_s[0],
                        a0.y + a1.y + a2.y + a3.y + b2_s[1]);
    }
}

extern "C" void kernel_launch(void* const* d_in, const int* in_sizes, int n_in,
                              void* d_out, int out_size)
{
    const float* x  = (const float*)d_in[0];
    const float* mp = (const float*)d_in[1];
    const float* u  = (const float*)d_in[2];
    const float* W0 = (const float*)d_in[3];
    const float* b0 = (const float*)d_in[4];
    const float* W1 = (const float*)d_in[5];
    const float* b1 = (const float*)d_in[6];
    const float* W2 = (const float*)d_in[7];
    const float* b2 = (const float*)d_in[8];
    float* out = (float*)d_out;

    static int inited = 0;
    if (!inited) {
        cudaFuncSetAttribute(tsdcd_fused, cudaFuncAttributeMaxDynamicSharedMemorySize, DYN_BYTES);
        inited = 1;
    }
    prep_w0<<<dim3(60, 4), 256>>>(W0);
    tsdcd_fused<<<dim3(NTILE, ND), TPB, DYN_BYTES>>>(x, mp, u, b0, W1, b1, W2, b2, out);
}

// round 14
// speedup vs baseline: 1.2795x; 1.1226x over previous
#include <cuda_runtime.h>
#include <cuda_fp16.h>
#include <cstdint>

#define NB     16
#define NTAU   10
#define ND     6
#define NN     512
#define NW     9
#define NHID   64
#define KC     54
#define TILE_M 64
#define NTILE  128
#define TPB    256
#define DYN_BYTES (33792 + 128)   // mainloop: A 8K + B0 8K + B1 8K; epilogue: hs 17408 + W1 16384

typedef unsigned long long ull;

// W0 pre-converted: [i*10+t] 8KB fp16 plane, swizzled [n][kk]
__device__ __align__(1024) unsigned char g_w0h[60 * 8192];

__device__ __forceinline__ uint32_t smem_u32(const void* p) {
    uint32_t a;
    asm("{ .reg .u64 t; cvta.to.shared.u64 t, %1; cvt.u32.u64 %0, t; }" : "=r"(a) : "l"(p));
    return a;
}
__device__ __forceinline__ ull ffma2(ull a, ull b, ull c) {
    ull d; asm("fma.rn.f32x2 %0, %1, %2, %3;" : "=l"(d) : "l"(a), "l"(b), "l"(c)); return d;
}
__device__ __forceinline__ ull pack2(float x) {
    ull d; asm("mov.b64 %0, {%1, %1};" : "=l"(d) : "f"(x)); return d;
}
__device__ __forceinline__ float2 unpack2(ull v) {
    float2 r; asm("mov.b64 {%0, %1}, %2;" : "=f"(r.x), "=f"(r.y) : "l"(v)); return r;
}
__device__ __forceinline__ uint32_t cvt_f16x2(float hi, float lo) {   // lo16 = lo
    uint32_t r; asm("cvt.rn.f16x2.f32 %0, %1, %2;" : "=r"(r) : "f"(hi), "f"(lo)); return r;
}
__device__ __forceinline__ float2 ldcs2(const float2* p) {
    float2 r; asm volatile("ld.global.cs.v2.f32 {%0,%1}, [%2];" : "=f"(r.x), "=f"(r.y) : "l"(p)); return r;
}
__device__ __forceinline__ void ldsm4(uint32_t a, uint32_t& r0, uint32_t& r1, uint32_t& r2, uint32_t& r3) {
    asm volatile("ldmatrix.sync.aligned.m8n8.x4.shared.b16 {%0,%1,%2,%3}, [%4];"
                 : "=r"(r0), "=r"(r1), "=r"(r2), "=r"(r3) : "r"(a));
}
__device__ __forceinline__ void mma_f16(float* d, uint32_t a0, uint32_t a1, uint32_t a2, uint32_t a3,
                                        uint32_t b0, uint32_t b1) {
    asm volatile("mma.sync.aligned.m16n8k16.row.col.f32.f16.f16.f32 "
                 "{%0,%1,%2,%3}, {%4,%5,%6,%7}, {%8,%9}, {%0,%1,%2,%3};"
                 : "+f"(d[0]), "+f"(d[1]), "+f"(d[2]), "+f"(d[3])
                 : "r"(a0), "r"(a1), "r"(a2), "r"(a3), "r"(b0), "r"(b1));
}
#define CP16(dst, src) asm volatile("cp.async.cg.shared.global [%0], [%1], 16;" :: "r"(dst), "l"(src))
#define CP_COMMIT()    asm volatile("cp.async.commit_group;" ::: "memory")
#define CP_WAIT0()     asm volatile("cp.async.wait_group 0;" ::: "memory")

// ------------ prep: W0 -> swizzled fp16 tile images (grid 60x4) ------------
__global__ void prep_w0(const float* __restrict__ W0)
{
    const int itx = blockIdx.x;                 // i*10 + t
    const int i = itx / 10, t = itx % 10;
    const float* src = W0 + ((size_t)i * 540 + t * KC) * NHID;
    unsigned char* dst = g_w0h + (size_t)itx * 8192;
    int e0 = blockIdx.y * 1024 + threadIdx.x;
    #pragma unroll
    for (int c = 0; c < 4; ++c) {
        int e = e0 + c * 256;
        int kk = e >> 6, n = e & 63;
        float v = (kk < KC) ? src[kk * 64 + n] : 0.f;
        uint32_t off = (uint32_t)(n * 128 + kk * 2) ^ ((uint32_t)(n & 7) << 4);
        *(uint16_t*)(dst + off) = __half_as_ushort(__float2half_rn(v));
    }
}

// ------------ fused: produce m in smem + fp16 tensor GEMM + layers 1/2 ------------
__global__ __launch_bounds__(TPB, 4)
void tsdcd_fused(const float* __restrict__ x,
                 const float* __restrict__ mask_param,
                 const float* __restrict__ u,
                 const float* __restrict__ b0,
                 const float* __restrict__ W1,
                 const float* __restrict__ b1,
                 const float* __restrict__ W2,
                 const float* __restrict__ b2,
                 float* __restrict__ out)
{
    extern __shared__ unsigned char dyn_raw[];
    __shared__ float E_s[NTAU * KC];
    __shared__ float x_s[2][6 * 12 * 17];
    __shared__ float b0_s[NHID], b1_s[NHID], W2_s[128], b2_s[2];
    __shared__ unsigned char lut_s[KC];
    __shared__ float2 po_s[TPB];

    const uint32_t raw_u = smem_u32(dyn_raw);
    const uint32_t dynb  = (raw_u + 127u) & ~127u;
    unsigned char* dyn = dyn_raw + (dynb - raw_u);
    // mainloop layout: A @0 (8K), B0 @8K, B1 @16K

    const int tid  = threadIdx.x;
    const int w    = tid >> 5;
    const int lane = tid & 31;
    const int i    = blockIdx.y;
    const int tile = blockIdx.x;
    const int tile0 = tile * TILE_M;
    const int n0    = tile0 >> 4;     // 4 n per tile

    // ---- one-time staging ----
    {   // zero A tile (8KB): padding cols kk 54..63 MUST stay 0
        float4 z = make_float4(0.f, 0.f, 0.f, 0.f);
        float4* az = (float4*)dyn;
        #pragma unroll
        for (int e = tid; e < 512; e += TPB) az[e] = z;
    }
    for (int e = tid; e < NTAU * KC; e += TPB) {
        int t = e / KC, r = e - t * KC;
        E_s[e] = __expf(-mask_param[(t * ND + i) * KC + r]);
    }
    if (tid < KC) lut_s[tid] = (unsigned char)((tid / NW) * 12 + tid % NW);
    if (tid < NHID) { b0_s[tid] = b0[i * NHID + tid]; b1_s[tid] = b1[i * NHID + tid]; }
    if (tid < 128) W2_s[tid] = W2[i * 128 + tid];
    if (tid < 2)   b2_s[tid] = b2[i * 2 + tid];

    float d[4][4];
    #pragma unroll
    for (int q = 0; q < 4; ++q)
        #pragma unroll
        for (int c = 0; c < 4; ++c) d[q][c] = 0.f;

    // per-lane ldmatrix geometry (4 row-groups x 2 n-halves)
    const int rg = w & 3;
    const int nh = w >> 2;
    const int rowA = rg * 16 + (lane & 15);
    const uint32_t arow = (uint32_t)rowA * 128;
    const uint32_t axr  = (uint32_t)(rowA & 7) << 4;
    const uint32_t colsel = (uint32_t)(lane >> 4) << 4;

    // ---- helpers ----
    auto stage_x = [&](int t) {
        float* xb = x_s[t & 1];
        #pragma unroll
        for (int it = 0; it < 5; ++it) {
            int e = tid + it * 256;
            if (e < 1152) {
                int colw = e % 12;
                int j = (e / 12) % 6;
                int bb = e / 72;
                int col = n0 + colw - 4;
                float v = 0.f;
                if ((unsigned)col < NN) v = x[((bb * NTAU + t) * ND + j) * NN + col];
                xb[(j * 12 + colw) * 17 + bb] = v;
            }
        }
    };
    auto load_u = [&](int t, float2* ur) {
        const float* ub = u + (size_t)(t * ND + i) * KC;
        #pragma unroll
        for (int it = 0; it < 7; ++it) {
            int p = tid + it * 256;
            if (p < 1728) {
                int r = (p * 4855) >> 17;     // p/27
                int q = p - r * 27;
                ur[it] = ldcs2((const float2*)(ub + (size_t)(tile0 + r) * 3240 + 2 * q));
            }
        }
    };
    auto cp_b = [&](int t) {
        const unsigned char* bsrc = g_w0h + (size_t)(i * 10 + t) * 8192;
        uint32_t bdst = dynb + 8192 + (uint32_t)(t & 1) * 8192;
        #pragma unroll
        for (int c = 0; c < 2; ++c)
            CP16(bdst + tid * 16 + c * 4096, bsrc + tid * 16 + c * 4096);
        CP_COMMIT();
    };
    auto do_math = [&](int t, const float2* ur) {   // m -> STS A (fp16x2)
        const float* xb = x_s[t & 1];
        #pragma unroll
        for (int it = 0; it < 7; ++it) {
            int p = tid + it * 256;
            if (p < 1728) {
                int r = (p * 4855) >> 17;
                int q = p - r * 27;
                int kk = 2 * q;
                float2 uv = ur[it];
                float2 ev = *(const float2*)&E_s[t * KC + kk];
                int nl = r >> 4, bb = r & 15;
                float x0 = xb[(lut_s[kk] + nl) * 17 + bb];
                float x1 = xb[(lut_s[kk + 1] + nl) * 17 + bb];
                float m0 = x0 * __fdividef(uv.x, fmaf(ev.x, 1.f - uv.x, uv.x));
                float m1 = x1 * __fdividef(uv.y, fmaf(ev.y, 1.f - uv.y, uv.y));
                uint32_t h2 = cvt_f16x2(m1, m0);            // lo16 = m0
                uint32_t off = (uint32_t)(r * 128 + 4 * q) ^ ((uint32_t)(r & 7) << 4);
                *(uint32_t*)(dyn + off) = h2;
            }
        }
    };
    auto consume = [&](int t) {
        uint32_t Abase = dynb;
        uint32_t Bbase = dynb + 8192 + (uint32_t)(t & 1) * 8192;
        #pragma unroll
        for (int k = 0; k < 4; ++k) {
            uint32_t colb = (uint32_t)k * 32 + colsel;
            uint32_t aa = Abase + arow + (colb ^ axr);
            uint32_t a0, a1, a2, a3;
            ldsm4(aa, a0, a1, a2, a3);
            #pragma unroll
            for (int g2 = 0; g2 < 2; ++g2) {
                int nrow = nh * 32 + g2 * 16 + (lane & 15);
                uint32_t ba = Bbase + (uint32_t)nrow * 128 + (colb ^ ((uint32_t)(nrow & 7) << 4));
                uint32_t b0r, b1r, b2r, b3r;
                ldsm4(ba, b0r, b1r, b2r, b3r);
                mma_f16(d[2 * g2],     a0, a1, a2, a3, b0r, b2r);
                mma_f16(d[2 * g2 + 1], a0, a1, a2, a3, b1r, b3r);
            }
        }
    };

    // ---- mainloop: 2 barriers / t; u reloaded in-place after consumption ----
    float2 ur[7];
    cp_b(0);
    stage_x(0);
    load_u(0, ur);
    #pragma unroll 2
    for (int t = 0; t < NTAU; ++t) {
        CP_WAIT0();                    // B(t) resident
        __syncthreads();               // barrier1: x_s(t)/A free (consume(t-1) done), B visible
        if (t + 1 < NTAU) {
            cp_b(t + 1);
            stage_x(t + 1);
        }
        do_math(t, ur);                // consumes ur(t)
        if (t + 1 < NTAU) load_u(t + 1, ur);   // refill; covered by barrier2 + consume(t)
        __syncthreads();               // barrier2: A(t) visible
        consume(t);
    }
    __syncthreads();

    // ---- epilogue: bias+relu -> h_s (stride 68) @dyn+0; W1 @dyn+17408 ----
    {
        float* hs = (float*)dyn;
        int r0 = rg * 16 + (lane >> 2);
        int c0 = nh * 32 + 2 * (lane & 3);
        #pragma unroll
        for (int oct = 0; oct < 4; ++oct) {
            int c = c0 + 8 * oct;
            float ba = b0_s[c], bbv = b0_s[c + 1];
            *(float2*)&hs[r0 * 68 + c]       = make_float2(fmaxf(d[oct][0] + ba, 0.f), fmaxf(d[oct][1] + bbv, 0.f));
            *(float2*)&hs[(r0 + 8) * 68 + c] = make_float2(fmaxf(d[oct][2] + ba, 0.f), fmaxf(d[oct][3] + bbv, 0.f));
        }
        const unsigned char* w1src = (const unsigned char*)(W1 + (size_t)i * NHID * NHID);
        uint32_t w1dst = dynb + 17408;
        #pragma unroll
        for (int c = 0; c < 4; ++c)
            CP16(w1dst + tid * 16 + c * 4096, w1src + tid * 16 + c * 4096);
        CP_COMMIT();
        CP_WAIT0();
    }
    __syncthreads();

    // ---- layers 1+2: 4 threads/token, each a 16-wide g-slice ----
    {
        const float* hs  = (const float*)dyn;
        const float* W1s = (const float*)(dyn + 17408);
        int rloc = tid >> 2;
        int gq   = tid & 3;
        const float* hrow = hs + rloc * 68;
        ull acc2[8];
        #pragma unroll
        for (int p = 0; p < 8; ++p) acc2[p] = 0ULL;
        #pragma unroll 8
        for (int k = 0; k < NHID; ++k) {
            ull hdup = pack2(hrow[k]);
            const ulonglong2* wr = (const ulonglong2*)(W1s + k * NHID + gq * 16);
            #pragma unroll
            for (int q = 0; q < 4; ++q) {
                ulonglong2 wv = wr[q];
                acc2[2 * q]     = ffma2(hdup, wv.x, acc2[2 * q]);
                acc2[2 * q + 1] = ffma2(hdup, wv.y, acc2[2 * q + 1]);
            }
        }
        float o0 = 0.f, o1 = 0.f;
        #pragma unroll
        for (int p = 0; p < 8; ++p) {
            float2 v = unpack2(acc2[p]);
            int g0 = gq * 16 + 2 * p;
            float v0 = fmaxf(v.x + b1_s[g0], 0.f);
            float v1 = fmaxf(v.y + b1_s[g0 + 1], 0.f);
            o0 = fmaf(v0, W2_s[g0 * 2],     o0);
            o1 = fmaf(v0, W2_s[g0 * 2 + 1], o1);
            o0 = fmaf(v1, W2_s[g0 * 2 + 2], o0);
            o1 = fmaf(v1, W2_s[g0 * 2 + 3], o1);
        }
        po_s[tid] = make_float2(o0, o1);
    }
    __syncthreads();
    if (tid < TILE_M) {
        float2 a0 = po_s[4 * tid],     a1 = po_s[4 * tid + 1];
        float2 a2 = po_s[4 * tid + 2], a3 = po_s[4 * tid + 3];
        int token = tile0 + tid;
        int bb = token & (NB - 1);
        int nn = token >> 4;
        ((float2*)out)[(size_t)(bb * ND + i) * NN + nn] =
            make_float2(a0.x + a1.x + a2.x + a3.x + b2_s[0],
                        a0.y + a1.y + a2.y + a3.y + b2_s[1]);
    }
}

extern "C" void kernel_launch(void* const* d_in, const int* in_sizes, int n_in,
                              void* d_out, int out_size)
{
    const float* x  = (const float*)d_in[0];
    const float* mp = (const float*)d_in[1];
    const float* u  = (const float*)d_in[2];
    const float* W0 = (const float*)d_in[3];
    const float* b0 = (const float*)d_in[4];
    const float* W1 = (const float*)d_in[5];
    const float* b1 = (const float*)d_in[6];
    const float* W2 = (const float*)d_in[7];
    const float* b2 = (const float*)d_in[8];
    float* out = (float*)d_out;

    static int inited = 0;
    if (!inited) {
        cudaFuncSetAttribute(tsdcd_fused, cudaFuncAttributeMaxDynamicSharedMemorySize, DYN_BYTES);
        inited = 1;
    }
    prep_w0<<<dim3(60, 4), 256>>>(W0);
    tsdcd_fused<<<dim3(NTILE, ND), TPB, DYN_BYTES>>>(x, mp, u, b0, W1, b1, W2, b2, out);
}